// round 5
// baseline (speedup 1.0000x reference)
#include <cuda_runtime.h>
#include <cuda_fp16.h>
#include <cstdint>

// ================================================================
// out[8192,4096] = A[8192,4096] (K-major) * W[4096,4096] (K-major)^T
// fp16 mma.sync m16n8k16, ldmatrix, XOR-swizzled smem,
// cp.async 4-stage pipeline, CTA tile 128x256, warp tile 64x64,
// one barrier per chunk. fp16 conversion in a pre-pass.
// ================================================================

#define M_DIM 8192
#define N_DIM 4096
#define K_DIM 4096

#define BM 128
#define BN 256
#define BK 64                        // fp16 per K chunk = 128 B/row
#define STAGES 4
#define NCHUNK (K_DIM / BK)          // 64

#define A_STAGE_BYTES (BM * 128)     // 16384
#define B_STAGE_BYTES (BN * 128)     // 32768
#define STAGE_BYTES   (A_STAGE_BYTES + B_STAGE_BYTES)      // 49152
#define SMEM_BYTES    (STAGES * STAGE_BYTES)               // 196608

__device__ __align__(1024) __half g_A[(size_t)M_DIM * K_DIM];
__device__ __align__(1024) __half g_B[(size_t)N_DIM * K_DIM];

__device__ __forceinline__ uint32_t smem_u32(const void* p) {
    uint32_t a;
    asm("{ .reg .u64 t; cvta.to.shared.u64 t, %1; cvt.u32.u64 %0, t; }" : "=r"(a) : "l"(p));
    return a;
}
__device__ __forceinline__ void cp_async16(uint32_t s, const void* g) {
    asm volatile("cp.async.cg.shared.global [%0], [%1], 16;" :: "r"(s), "l"(g));
}
__device__ __forceinline__ void cp_commit() {
    asm volatile("cp.async.commit_group;" ::: "memory");
}
template <int N>
__device__ __forceinline__ void cp_wait() {
    asm volatile("cp.async.wait_group %0;" :: "n"(N) : "memory");
}
__device__ __forceinline__ void ldsm_x4(uint32_t r[4], uint32_t addr) {
    asm volatile("ldmatrix.sync.aligned.m8n8.x4.shared.b16 {%0,%1,%2,%3}, [%4];"
                 : "=r"(r[0]), "=r"(r[1]), "=r"(r[2]), "=r"(r[3]) : "r"(addr));
}
__device__ __forceinline__ void mma_f16(float c[4], const uint32_t a[4],
                                        uint32_t b0, uint32_t b1) {
    asm volatile(
        "mma.sync.aligned.m16n8k16.row.col.f32.f16.f16.f32 "
        "{%0,%1,%2,%3}, {%4,%5,%6,%7}, {%8,%9}, {%0,%1,%2,%3};"
        : "+f"(c[0]), "+f"(c[1]), "+f"(c[2]), "+f"(c[3])
        : "r"(a[0]), "r"(a[1]), "r"(a[2]), "r"(a[3]), "r"(b0), "r"(b1));
}

__global__ void __launch_bounds__(256) cvt_f16_kernel(
    const float4* __restrict__ in, __half2* __restrict__ out, int n4)
{
    int stride = gridDim.x * blockDim.x;
    for (int i = blockIdx.x * blockDim.x + threadIdx.x; i < n4; i += stride) {
        float4 v = in[i];
        out[2 * i]     = __floats2half2_rn(v.x, v.y);
        out[2 * i + 1] = __floats2half2_rn(v.z, v.w);
    }
}

extern __shared__ char smemc[];

__global__ void __launch_bounds__(256, 1) agg_gemm_kernel(
    const __half* __restrict__ A,    // [M, K] fp16
    const __half* __restrict__ W,    // [N, K] fp16
    float* __restrict__ out)         // [M, N] fp32
{
    const int t = threadIdx.x;
    const int wid = t >> 5;
    const int lane = t & 31;
    const int wm = wid & 1;          // warp M (0..1): 64 rows
    const int wn = wid >> 1;         // warp N (0..3): 64 cols
    const int g = lane >> 2;
    const int tig = lane & 3;

    const int m0 = blockIdx.y * BM;
    const int n0 = blockIdx.x * BN;

    const uint32_t sb = smem_u32(smemc);

    // cp.async mapping: thread covers (row = t>>3 (+32i), seg = t&7) 16B chunks
    const int seg = t & 7;
    const int rbase = t >> 3;

    auto load_stage = [&](int stage, int c) {
        const int k0 = c * BK;
        const uint32_t sA = sb + (uint32_t)stage * STAGE_BYTES;
        const uint32_t sB = sA + A_STAGE_BYTES;
        #pragma unroll
        for (int i = 0; i < 4; i++) {            // A: 128 rows
            const int row = rbase + i * 32;
            const uint32_t soff = (uint32_t)row * 128u + (uint32_t)((seg ^ (row & 7)) * 16);
            cp_async16(sA + soff, A + (size_t)(m0 + row) * K_DIM + k0 + seg * 8);
        }
        #pragma unroll
        for (int i = 0; i < 8; i++) {            // B: 256 rows
            const int row = rbase + i * 32;
            const uint32_t soff = (uint32_t)row * 128u + (uint32_t)((seg ^ (row & 7)) * 16);
            cp_async16(sB + soff, W + (size_t)(n0 + row) * K_DIM + k0 + seg * 8);
        }
    };

    float acc[4][8][4];
    #pragma unroll
    for (int mi = 0; mi < 4; mi++)
        #pragma unroll
        for (int ni = 0; ni < 8; ni++)
            #pragma unroll
            for (int q = 0; q < 4; q++) acc[mi][ni][q] = 0.0f;

    // ldmatrix lane addressing: row = base + (lane&15); chunk = ks*2 + (lane>>4)
    // swizzle: chunk ^= (row & 7) == (lane & 7)
    const int lrow = lane & 15;
    const int lhi = lane >> 4;
    const int lsw = lane & 7;
    const uint32_t a_row_off = (uint32_t)(wm * 64 + lrow) * 128u;
    const uint32_t b_row_off = (uint32_t)A_STAGE_BYTES + (uint32_t)(wn * 64 + lrow) * 128u;

    #pragma unroll
    for (int ps = 0; ps < STAGES - 1; ps++) {
        load_stage(ps, ps);
        cp_commit();
    }

    int cstage = 0, fstage = STAGES - 1;
    for (int c = 0; c < NCHUNK; c++) {
        cp_wait<STAGES - 2>();
        __syncthreads();          // single barrier per chunk (see theory note)

        const int fetch = c + STAGES - 1;
        if (fetch < NCHUNK) load_stage(fstage, fetch);
        cp_commit();
        if (++fstage == STAGES) fstage = 0;

        const uint32_t sbase = sb + (uint32_t)cstage * STAGE_BYTES;
        if (++cstage == STAGES) cstage = 0;

        #pragma unroll
        for (int ks = 0; ks < 4; ks++) {
            const uint32_t chunk = (uint32_t)(((ks * 2 + lhi) ^ lsw) * 16);
            uint32_t a[4][4];
            #pragma unroll
            for (int mi = 0; mi < 4; mi++)
                ldsm_x4(a[mi], sbase + a_row_off + (uint32_t)(mi * 16 * 128) + chunk);
            uint32_t b[4][4];
            #pragma unroll
            for (int p = 0; p < 4; p++)
                ldsm_x4(b[p], sbase + b_row_off + (uint32_t)(p * 16 * 128) + chunk);
            // b[p] regs: {tile(2p).b0, tile(2p+1).b0, tile(2p).b1, tile(2p+1).b1}
            #pragma unroll
            for (int mi = 0; mi < 4; mi++) {
                #pragma unroll
                for (int p = 0; p < 4; p++) {
                    mma_f16(acc[mi][2 * p],     a[mi], b[p][0], b[p][2]);
                    mma_f16(acc[mi][2 * p + 1], a[mi], b[p][1], b[p][3]);
                }
            }
        }
    }

    // ---------------- epilogue ----------------
    #pragma unroll
    for (int mi = 0; mi < 4; mi++) {
        const int row = m0 + wm * 64 + mi * 16 + g;
        #pragma unroll
        for (int ni = 0; ni < 8; ni++) {
            const int col = n0 + wn * 64 + ni * 8 + 2 * tig;
            float2 lo = make_float2(acc[mi][ni][0], acc[mi][ni][1]);
            float2 hi = make_float2(acc[mi][ni][2], acc[mi][ni][3]);
            *reinterpret_cast<float2*>(out + (size_t)row * N_DIM + col) = lo;
            *reinterpret_cast<float2*>(out + (size_t)(row + 8) * N_DIM + col) = hi;
        }
    }
}

extern "C" void kernel_launch(void* const* d_in, const int* in_sizes, int n_in,
                              void* d_out, int out_size) {
    const float* A_in = (const float*)d_in[0];   // [8,1024,4096] = [8192,4096]
    const float* W_in = (const float*)d_in[1];   // [4096,4096] K-major
    float* out = (float*)d_out;

    void *pA = nullptr, *pB = nullptr;
    cudaGetSymbolAddress(&pA, g_A);
    cudaGetSymbolAddress(&pB, g_B);

    cudaFuncSetAttribute(agg_gemm_kernel,
                         cudaFuncAttributeMaxDynamicSharedMemorySize, SMEM_BYTES);

    cvt_f16_kernel<<<1184, 256>>>((const float4*)A_in, (__half2*)pA,
                                  (int)(((size_t)M_DIM * K_DIM) / 4));
    cvt_f16_kernel<<<1184, 256>>>((const float4*)W_in, (__half2*)pB,
                                  (int)(((size_t)N_DIM * K_DIM) / 4));

    dim3 grid(N_DIM / BN, M_DIM / BM);   // (16, 64)
    agg_gemm_kernel<<<grid, 256, SMEM_BYTES>>>((const __half*)pA, (const __half*)pB, out);
}

// round 6
// speedup vs baseline: 1.1160x; 1.1160x over previous
#include <cuda_runtime.h>
#include <cuda.h>
#include <cuda_fp16.h>
#include <cstdint>

// ================================================================
// out[8192,4096] = A[8192,4096] (K-major) * W[4096,4096] (K-major)^T
// fp16 mma.sync m16n8k16 + ldmatrix + TMA (SW128) 3-stage mbarrier
// pipeline, CTA 128x128, warp 64x32, 2 CTAs/SM, 1 barrier/chunk.
// fp16 conversion in a pre-pass.
// ================================================================

#define M_DIM 8192
#define N_DIM 4096
#define K_DIM 4096

#define BM 128
#define BN 128
#define BK 64                        // fp16 per K chunk = 128 B/row
#define STAGES 3
#define NCHUNK (K_DIM / BK)          // 64

#define A_STAGE_BYTES (BM * 128)     // 16384
#define B_STAGE_BYTES (BN * 128)     // 16384
#define STAGE_BYTES   (A_STAGE_BYTES + B_STAGE_BYTES)      // 32768
#define SMEM_TILE_OFF 1024
#define SMEM_BYTES    (SMEM_TILE_OFF + STAGES * STAGE_BYTES)  // 99328 -> 2 CTAs/SM

__device__ __align__(1024) __half g_A[(size_t)M_DIM * K_DIM];
__device__ __align__(1024) __half g_B[(size_t)N_DIM * K_DIM];

__device__ __forceinline__ uint32_t smem_u32(const void* p) {
    uint32_t a;
    asm("{ .reg .u64 t; cvta.to.shared.u64 t, %1; cvt.u32.u64 %0, t; }" : "=r"(a) : "l"(p));
    return a;
}
#define MBARRIER_INIT(a, n) \
    asm volatile("mbarrier.init.shared.b64 [%0], %1;" :: "r"((uint32_t)(a)), "r"((uint32_t)(n)) : "memory")
#define MBARRIER_EXPECT_TX(a, b) \
    asm volatile("mbarrier.arrive.expect_tx.shared.b64 _, [%0], %1;" :: "r"((uint32_t)(a)), "r"((uint32_t)(b)) : "memory")
#define MBARRIER_WAIT(a, ph) do {                                                   \
    uint32_t _m = (uint32_t)(a), _p = (uint32_t)(ph), _d;                           \
    asm volatile("{\n\t.reg .pred p;\n\t"                                           \
        "mbarrier.try_wait.parity.acquire.cta.shared::cta.b64 p, [%1], %2;\n\t"     \
        "selp.b32 %0, 1, 0, p;\n\t}" : "=r"(_d) : "r"(_m), "r"(_p) : "memory");     \
    if (!_d) {                                                                       \
        asm volatile("{\n\t.reg .pred P1;\n\t"                                      \
            "WL_%=:\n\t"                                                            \
            "mbarrier.try_wait.parity.acquire.cta.shared::cta.b64 P1, [%0], %1, 0x989680;\n\t" \
            "@P1 bra.uni WD_%=;\n\t bra.uni WL_%=;\n\t WD_%=:\n\t}"                 \
            :: "r"(_m), "r"(_p) : "memory");                                        \
    }                                                                                \
} while (0)
#define TMA_LOAD_2D(smem, map, c0, c1, mbar)                                        \
    asm volatile("cp.async.bulk.tensor.2d.shared::cta.global.tile.mbarrier::complete_tx::bytes " \
        "[%0], [%1, {%2, %3}], [%4];"                                               \
        :: "r"((uint32_t)(smem)), "l"(map), "r"((int)(c0)), "r"((int)(c1)),         \
           "r"((uint32_t)(mbar)) : "memory")

__device__ __forceinline__ void ldsm_x4(uint32_t r[4], uint32_t addr) {
    asm volatile("ldmatrix.sync.aligned.m8n8.x4.shared.b16 {%0,%1,%2,%3}, [%4];"
                 : "=r"(r[0]), "=r"(r[1]), "=r"(r[2]), "=r"(r[3]) : "r"(addr));
}
__device__ __forceinline__ void mma_f16(float c[4], const uint32_t a[4],
                                        uint32_t b0, uint32_t b1) {
    asm volatile(
        "mma.sync.aligned.m16n8k16.row.col.f32.f16.f16.f32 "
        "{%0,%1,%2,%3}, {%4,%5,%6,%7}, {%8,%9}, {%0,%1,%2,%3};"
        : "+f"(c[0]), "+f"(c[1]), "+f"(c[2]), "+f"(c[3])
        : "r"(a[0]), "r"(a[1]), "r"(a[2]), "r"(a[3]), "r"(b0), "r"(b1));
}

__global__ void __launch_bounds__(256) cvt_f16_kernel(
    const float4* __restrict__ in, __half2* __restrict__ out, int n4)
{
    int stride = gridDim.x * blockDim.x;
    for (int i = blockIdx.x * blockDim.x + threadIdx.x; i < n4; i += stride) {
        float4 v = in[i];
        out[2 * i]     = __floats2half2_rn(v.x, v.y);
        out[2 * i + 1] = __floats2half2_rn(v.z, v.w);
    }
}

extern __shared__ char smemc[];

__global__ void __launch_bounds__(256, 2) agg_gemm_kernel(
    const __grid_constant__ CUtensorMap tma_a,
    const __grid_constant__ CUtensorMap tma_b,
    float* __restrict__ out)
{
    const int t = threadIdx.x;
    const int wid = t >> 5;
    const int lane = t & 31;
    const int wm = wid & 1;          // warp M (0..1): 64 rows
    const int wn = wid >> 1;         // warp N (0..3): 32 cols
    const int g = lane >> 2;
    const int tig = lane & 3;

    const int m0 = blockIdx.y * BM;
    const int n0 = blockIdx.x * BN;

    const uint32_t sb = smem_u32(smemc);
    const uint32_t mbar0 = sb;                    // 3 mbarriers at sb + 8*s
    const uint32_t tiles = sb + SMEM_TILE_OFF;

    if (t == 0) {
        #pragma unroll
        for (int s = 0; s < STAGES; s++) MBARRIER_INIT(mbar0 + 8 * s, 1);
    }
    __syncthreads();

    // prologue: chunks 0,1 into stages 0,1
    if (t == 0) {
        #pragma unroll
        for (int ps = 0; ps < STAGES - 1; ps++) {
            uint32_t mb = mbar0 + 8 * ps;
            uint32_t sbase = tiles + ps * STAGE_BYTES;
            MBARRIER_EXPECT_TX(mb, STAGE_BYTES);
            TMA_LOAD_2D(sbase,                 &tma_a, ps * BK, m0, mb);
            TMA_LOAD_2D(sbase + A_STAGE_BYTES, &tma_b, ps * BK, n0, mb);
        }
    }

    float acc[4][4][4];
    #pragma unroll
    for (int mi = 0; mi < 4; mi++)
        #pragma unroll
        for (int ni = 0; ni < 4; ni++)
            #pragma unroll
            for (int q = 0; q < 4; q++) acc[mi][ni][q] = 0.0f;

    // ldmatrix lane addressing: row = base + (lane&15); chunk = ks*2 + (lane>>4)
    // swizzle (matches TMA SW128): chunk16 ^= (row & 7)
    const int lrow = lane & 15;
    const int lhi = lane >> 4;
    const int lsw = lane & 7;
    const uint32_t a_row_off = (uint32_t)(wm * 64 + lrow) * 128u;
    const uint32_t b_row_off = (uint32_t)A_STAGE_BYTES + (uint32_t)(wn * 32 + lrow) * 128u;

    int cstage = 0, cphase = 0;      // consumer stage/parity
    int fstage = STAGES - 1;         // fetch target stage for chunk c+2

    for (int c = 0; c < NCHUNK; c++) {
        MBARRIER_WAIT(mbar0 + 8 * cstage, cphase);
        __syncthreads();   // all warps done with chunk c-1 -> stage fstage reusable

        const int fetch = c + STAGES - 1;
        if (t == 0 && fetch < NCHUNK) {
            uint32_t mb = mbar0 + 8 * fstage;
            uint32_t sbase = tiles + fstage * STAGE_BYTES;
            MBARRIER_EXPECT_TX(mb, STAGE_BYTES);
            TMA_LOAD_2D(sbase,                 &tma_a, fetch * BK, m0, mb);
            TMA_LOAD_2D(sbase + A_STAGE_BYTES, &tma_b, fetch * BK, n0, mb);
        }
        if (++fstage == STAGES) fstage = 0;

        const uint32_t sbase = tiles + (uint32_t)cstage * STAGE_BYTES;
        if (++cstage == STAGES) { cstage = 0; cphase ^= 1; }

        #pragma unroll
        for (int ks = 0; ks < 4; ks++) {
            const uint32_t chunk = (uint32_t)(((ks * 2 + lhi) ^ lsw) * 16);
            uint32_t a[4][4];
            #pragma unroll
            for (int mi = 0; mi < 4; mi++)
                ldsm_x4(a[mi], sbase + a_row_off + (uint32_t)(mi * 16 * 128) + chunk);
            uint32_t b[2][4];
            #pragma unroll
            for (int p = 0; p < 2; p++)
                ldsm_x4(b[p], sbase + b_row_off + (uint32_t)(p * 16 * 128) + chunk);
            #pragma unroll
            for (int mi = 0; mi < 4; mi++) {
                mma_f16(acc[mi][0], a[mi], b[0][0], b[0][2]);
                mma_f16(acc[mi][1], a[mi], b[0][1], b[0][3]);
                mma_f16(acc[mi][2], a[mi], b[1][0], b[1][2]);
                mma_f16(acc[mi][3], a[mi], b[1][1], b[1][3]);
            }
        }
    }

    // ---------------- epilogue ----------------
    #pragma unroll
    for (int mi = 0; mi < 4; mi++) {
        const int row = m0 + wm * 64 + mi * 16 + g;
        #pragma unroll
        for (int ni = 0; ni < 4; ni++) {
            const int col = n0 + wn * 32 + ni * 8 + 2 * tig;
            float2 lo = make_float2(acc[mi][ni][0], acc[mi][ni][1]);
            float2 hi = make_float2(acc[mi][ni][2], acc[mi][ni][3]);
            *reinterpret_cast<float2*>(out + (size_t)row * N_DIM + col) = lo;
            *reinterpret_cast<float2*>(out + (size_t)(row + 8) * N_DIM + col) = hi;
        }
    }
}

// ---------------- host ----------------
typedef CUresult (*PFN_EncodeTiled)(
    CUtensorMap*, CUtensorMapDataType, cuuint32_t, void*,
    const cuuint64_t*, const cuuint64_t*, const cuuint32_t*, const cuuint32_t*,
    CUtensorMapInterleave, CUtensorMapSwizzle, CUtensorMapL2promotion, CUtensorMapFloatOOBfill);

static void encode_2d_f16(PFN_EncodeTiled enc, CUtensorMap* map, void* ptr,
                          uint64_t dim0, uint64_t dim1, uint32_t box0, uint32_t box1) {
    cuuint64_t dims[2]    = {dim0, dim1};
    cuuint64_t strides[1] = {dim0 * sizeof(__half)};
    cuuint32_t box[2]     = {box0, box1};
    cuuint32_t estr[2]    = {1, 1};
    enc(map, CU_TENSOR_MAP_DATA_TYPE_FLOAT16, 2, ptr, dims, strides, box, estr,
        CU_TENSOR_MAP_INTERLEAVE_NONE, CU_TENSOR_MAP_SWIZZLE_128B,
        CU_TENSOR_MAP_L2_PROMOTION_L2_128B, CU_TENSOR_MAP_FLOAT_OOB_FILL_NONE);
}

extern "C" void kernel_launch(void* const* d_in, const int* in_sizes, int n_in,
                              void* d_out, int out_size) {
    const float* A_in = (const float*)d_in[0];   // [8,1024,4096] = [8192,4096]
    const float* W_in = (const float*)d_in[1];   // [4096,4096] K-major
    float* out = (float*)d_out;

    void *pA = nullptr, *pB = nullptr;
    cudaGetSymbolAddress(&pA, g_A);
    cudaGetSymbolAddress(&pB, g_B);

    void* fn = nullptr;
    cudaDriverEntryPointQueryResult st;
    cudaGetDriverEntryPointByVersion("cuTensorMapEncodeTiled", &fn, 12000,
                                     cudaEnableDefault, &st);
    PFN_EncodeTiled enc = (PFN_EncodeTiled)fn;

    CUtensorMap mapA, mapB;
    encode_2d_f16(enc, &mapA, pA, K_DIM, M_DIM, BK, BM);
    encode_2d_f16(enc, &mapB, pB, K_DIM, N_DIM, BK, BN);

    cudaFuncSetAttribute(agg_gemm_kernel,
                         cudaFuncAttributeMaxDynamicSharedMemorySize, SMEM_BYTES);

    cvt_f16_kernel<<<1184, 256>>>((const float4*)A_in, (__half2*)pA,
                                  (int)(((size_t)M_DIM * K_DIM) / 4));
    cvt_f16_kernel<<<1184, 256>>>((const float4*)W_in, (__half2*)pB,
                                  (int)(((size_t)N_DIM * K_DIM) / 4));

    dim3 grid(N_DIM / BN, M_DIM / BM);   // (32, 64)
    agg_gemm_kernel<<<grid, 256, SMEM_BYTES>>>(mapA, mapB, out);
}

// round 7
// speedup vs baseline: 1.1209x; 1.0043x over previous
#include <cuda_runtime.h>
#include <cuda.h>
#include <cuda_fp16.h>
#include <cstdint>

// ================================================================
// out[8192,4096] = A[8192,4096] (K-major) * W[4096,4096] (K-major)^T
// fp16 mma.sync m16n8k16 + ldmatrix + TMA (SW128), 3-stage
// producer/consumer mbarrier pipeline (full tx-barriers + empty
// barriers with 8 warp-arrives), NO CTA-wide barrier in main loop.
// CTA 128x128, warp 64x32, 2 CTAs/SM. fp16 conversion pre-pass.
// ================================================================

#define M_DIM 8192
#define N_DIM 4096
#define K_DIM 4096

#define BM 128
#define BN 128
#define BK 64                        // fp16 per K chunk = 128 B/row
#define STAGES 3
#define NCHUNK (K_DIM / BK)          // 64
#define NWARPS 8

#define A_STAGE_BYTES (BM * 128)     // 16384
#define B_STAGE_BYTES (BN * 128)     // 16384
#define STAGE_BYTES   (A_STAGE_BYTES + B_STAGE_BYTES)      // 32768
#define SMEM_TILE_OFF 1024
#define SMEM_BYTES    (SMEM_TILE_OFF + STAGES * STAGE_BYTES)  // 99328 -> 2 CTAs/SM

__device__ __align__(1024) __half g_A[(size_t)M_DIM * K_DIM];
__device__ __align__(1024) __half g_B[(size_t)N_DIM * K_DIM];

__device__ __forceinline__ uint32_t smem_u32(const void* p) {
    uint32_t a;
    asm("{ .reg .u64 t; cvta.to.shared.u64 t, %1; cvt.u32.u64 %0, t; }" : "=r"(a) : "l"(p));
    return a;
}
#define MBARRIER_INIT(a, n) \
    asm volatile("mbarrier.init.shared.b64 [%0], %1;" :: "r"((uint32_t)(a)), "r"((uint32_t)(n)) : "memory")
#define MBARRIER_EXPECT_TX(a, b) \
    asm volatile("mbarrier.arrive.expect_tx.shared.b64 _, [%0], %1;" :: "r"((uint32_t)(a)), "r"((uint32_t)(b)) : "memory")
#define MBARRIER_ARRIVE(a) \
    asm volatile("mbarrier.arrive.shared.b64 _, [%0];" :: "r"((uint32_t)(a)) : "memory")

#define MBARRIER_WAIT_ACQ(a, ph) do {                                               \
    uint32_t _m = (uint32_t)(a), _p = (uint32_t)(ph), _d;                           \
    asm volatile("{\n\t.reg .pred p;\n\t"                                           \
        "mbarrier.try_wait.parity.acquire.cta.shared::cta.b64 p, [%1], %2;\n\t"     \
        "selp.b32 %0, 1, 0, p;\n\t}" : "=r"(_d) : "r"(_m), "r"(_p) : "memory");     \
    if (!_d) {                                                                       \
        asm volatile("{\n\t.reg .pred P1;\n\t"                                      \
            "WL_%=:\n\t"                                                            \
            "mbarrier.try_wait.parity.acquire.cta.shared::cta.b64 P1, [%0], %1, 0x989680;\n\t" \
            "@P1 bra.uni WD_%=;\n\t bra.uni WL_%=;\n\t WD_%=:\n\t}"                 \
            :: "r"(_m), "r"(_p) : "memory");                                        \
    }                                                                                \
} while (0)

#define MBARRIER_WAIT_RLX(a, ph) do {                                               \
    uint32_t _m = (uint32_t)(a), _p = (uint32_t)(ph), _d;                           \
    asm volatile("{\n\t.reg .pred p;\n\t"                                           \
        "mbarrier.try_wait.parity.relaxed.cta.shared::cta.b64 p, [%1], %2, 0x989680;\n\t" \
        "selp.b32 %0, 1, 0, p;\n\t}" : "=r"(_d) : "r"(_m), "r"(_p) : "memory");     \
    if (!_d) {                                                                       \
        asm volatile("{\n\t.reg .pred P1;\n\t"                                      \
            "WL_%=:\n\t"                                                            \
            "mbarrier.try_wait.parity.relaxed.cta.shared::cta.b64 P1, [%0], %1, 0x989680;\n\t" \
            "@P1 bra.uni WD_%=;\n\t bra.uni WL_%=;\n\t WD_%=:\n\t}"                 \
            :: "r"(_m), "r"(_p) : "memory");                                        \
    }                                                                                \
} while (0)

#define TMA_LOAD_2D(smem, map, c0, c1, mbar)                                        \
    asm volatile("cp.async.bulk.tensor.2d.shared::cta.global.tile.mbarrier::complete_tx::bytes " \
        "[%0], [%1, {%2, %3}], [%4];"                                               \
        :: "r"((uint32_t)(smem)), "l"(map), "r"((int)(c0)), "r"((int)(c1)),         \
           "r"((uint32_t)(mbar)) : "memory")

__device__ __forceinline__ void ldsm_x4(uint32_t r[4], uint32_t addr) {
    asm volatile("ldmatrix.sync.aligned.m8n8.x4.shared.b16 {%0,%1,%2,%3}, [%4];"
                 : "=r"(r[0]), "=r"(r[1]), "=r"(r[2]), "=r"(r[3]) : "r"(addr));
}
__device__ __forceinline__ void mma_f16(float c[4], const uint32_t a[4],
                                        uint32_t b0, uint32_t b1) {
    asm volatile(
        "mma.sync.aligned.m16n8k16.row.col.f32.f16.f16.f32 "
        "{%0,%1,%2,%3}, {%4,%5,%6,%7}, {%8,%9}, {%0,%1,%2,%3};"
        : "+f"(c[0]), "+f"(c[1]), "+f"(c[2]), "+f"(c[3])
        : "r"(a[0]), "r"(a[1]), "r"(a[2]), "r"(a[3]), "r"(b0), "r"(b1));
}

__global__ void __launch_bounds__(256) cvt_f16_kernel(
    const float4* __restrict__ in, __half2* __restrict__ out, int n4)
{
    int stride = gridDim.x * blockDim.x;
    for (int i = blockIdx.x * blockDim.x + threadIdx.x; i < n4; i += stride) {
        float4 v = in[i];
        out[2 * i]     = __floats2half2_rn(v.x, v.y);
        out[2 * i + 1] = __floats2half2_rn(v.z, v.w);
    }
}

extern __shared__ char smemc[];

// smem barrier layout: full[s] = sb + 16*s, empty[s] = sb + 16*s + 8
__global__ void __launch_bounds__(256, 2) agg_gemm_kernel(
    const __grid_constant__ CUtensorMap tma_a,
    const __grid_constant__ CUtensorMap tma_b,
    float* __restrict__ out)
{
    const int t = threadIdx.x;
    const int wid = t >> 5;
    const int lane = t & 31;
    const int wm = wid & 1;          // warp M (0..1): 64 rows
    const int wn = wid >> 1;         // warp N (0..3): 32 cols
    const int g = lane >> 2;
    const int tig = lane & 3;

    const int m0 = blockIdx.y * BM;
    const int n0 = blockIdx.x * BN;

    const uint32_t sb = smem_u32(smemc);
    const uint32_t tiles = sb + SMEM_TILE_OFF;

    if (t == 0) {
        #pragma unroll
        for (int s = 0; s < STAGES; s++) {
            MBARRIER_INIT(sb + 16 * s, 1);           // full: tx-based
            MBARRIER_INIT(sb + 16 * s + 8, NWARPS);  // empty: 8 warp arrives
        }
    }
    __syncthreads();

    // ---- producer cursor (phase starts 1: first STAGES waits pass) ----
    int pstage = 0, pphase = 1;
    auto produce = [&](int chunk) {
        const uint32_t fullb = sb + 16 * pstage;
        MBARRIER_WAIT_RLX(fullb + 8, pphase);
        MBARRIER_EXPECT_TX(fullb, STAGE_BYTES);
        const uint32_t sbase = tiles + (uint32_t)pstage * STAGE_BYTES;
        TMA_LOAD_2D(sbase,                 &tma_a, chunk * BK, m0, fullb);
        TMA_LOAD_2D(sbase + A_STAGE_BYTES, &tma_b, chunk * BK, n0, fullb);
        if (++pstage == STAGES) { pstage = 0; pphase ^= 1; }
    };

    if (t == 0) {
        #pragma unroll
        for (int ps = 0; ps < STAGES - 1; ps++) produce(ps);
    }

    float acc[4][4][4];
    #pragma unroll
    for (int mi = 0; mi < 4; mi++)
        #pragma unroll
        for (int ni = 0; ni < 4; ni++)
            #pragma unroll
            for (int q = 0; q < 4; q++) acc[mi][ni][q] = 0.0f;

    // ldmatrix lane addressing: row = base + (lane&15); chunk16 ^= (row & 7)
    const int lrow = lane & 15;
    const int lhi = lane >> 4;
    const int lsw = lane & 7;
    const uint32_t a_row_off = (uint32_t)(wm * 64 + lrow) * 128u;
    const uint32_t b_row_off = (uint32_t)A_STAGE_BYTES + (uint32_t)(wn * 32 + lrow) * 128u;

    int cstage = 0, cphase = 0;

    for (int c = 0; c < NCHUNK; c++) {
        // producer: fetch chunk c+2 (stage ring provides backpressure)
        const int fetch = c + STAGES - 1;
        if (t == 0 && fetch < NCHUNK) produce(fetch);

        const uint32_t fullb = sb + 16 * cstage;
        MBARRIER_WAIT_ACQ(fullb, cphase);

        const uint32_t sbase = tiles + (uint32_t)cstage * STAGE_BYTES;

        #pragma unroll
        for (int ks = 0; ks < 4; ks++) {
            const uint32_t chunk = (uint32_t)(((ks * 2 + lhi) ^ lsw) * 16);
            uint32_t a[4][4];
            #pragma unroll
            for (int mi = 0; mi < 4; mi++)
                ldsm_x4(a[mi], sbase + a_row_off + (uint32_t)(mi * 16 * 128) + chunk);
            uint32_t b[2][4];
            #pragma unroll
            for (int p = 0; p < 2; p++)
                ldsm_x4(b[p], sbase + b_row_off + (uint32_t)(p * 16 * 128) + chunk);
            #pragma unroll
            for (int mi = 0; mi < 4; mi++) {
                mma_f16(acc[mi][0], a[mi], b[0][0], b[0][2]);
                mma_f16(acc[mi][1], a[mi], b[0][1], b[0][3]);
                mma_f16(acc[mi][2], a[mi], b[1][0], b[1][2]);
                mma_f16(acc[mi][3], a[mi], b[1][1], b[1][3]);
            }
        }

        // this warp is done with the stage
        if (lane == 0) MBARRIER_ARRIVE(fullb + 8);
        if (++cstage == STAGES) { cstage = 0; cphase ^= 1; }
    }

    // ---------------- epilogue ----------------
    #pragma unroll
    for (int mi = 0; mi < 4; mi++) {
        const int row = m0 + wm * 64 + mi * 16 + g;
        #pragma unroll
        for (int ni = 0; ni < 4; ni++) {
            const int col = n0 + wn * 32 + ni * 8 + 2 * tig;
            float2 lo = make_float2(acc[mi][ni][0], acc[mi][ni][1]);
            float2 hi = make_float2(acc[mi][ni][2], acc[mi][ni][3]);
            *reinterpret_cast<float2*>(out + (size_t)row * N_DIM + col) = lo;
            *reinterpret_cast<float2*>(out + (size_t)(row + 8) * N_DIM + col) = hi;
        }
    }
}

// ---------------- host ----------------
typedef CUresult (*PFN_EncodeTiled)(
    CUtensorMap*, CUtensorMapDataType, cuuint32_t, void*,
    const cuuint64_t*, const cuuint64_t*, const cuuint32_t*, const cuuint32_t*,
    CUtensorMapInterleave, CUtensorMapSwizzle, CUtensorMapL2promotion, CUtensorMapFloatOOBfill);

static void encode_2d_f16(PFN_EncodeTiled enc, CUtensorMap* map, void* ptr,
                          uint64_t dim0, uint64_t dim1, uint32_t box0, uint32_t box1) {
    cuuint64_t dims[2]    = {dim0, dim1};
    cuuint64_t strides[1] = {dim0 * sizeof(__half)};
    cuuint32_t box[2]     = {box0, box1};
    cuuint32_t estr[2]    = {1, 1};
    enc(map, CU_TENSOR_MAP_DATA_TYPE_FLOAT16, 2, ptr, dims, strides, box, estr,
        CU_TENSOR_MAP_INTERLEAVE_NONE, CU_TENSOR_MAP_SWIZZLE_128B,
        CU_TENSOR_MAP_L2_PROMOTION_L2_128B, CU_TENSOR_MAP_FLOAT_OOB_FILL_NONE);
}

extern "C" void kernel_launch(void* const* d_in, const int* in_sizes, int n_in,
                              void* d_out, int out_size) {
    const float* A_in = (const float*)d_in[0];   // [8,1024,4096] = [8192,4096]
    const float* W_in = (const float*)d_in[1];   // [4096,4096] K-major
    float* out = (float*)d_out;

    void *pA = nullptr, *pB = nullptr;
    cudaGetSymbolAddress(&pA, g_A);
    cudaGetSymbolAddress(&pB, g_B);

    void* fn = nullptr;
    cudaDriverEntryPointQueryResult st;
    cudaGetDriverEntryPointByVersion("cuTensorMapEncodeTiled", &fn, 12000,
                                     cudaEnableDefault, &st);
    PFN_EncodeTiled enc = (PFN_EncodeTiled)fn;

    CUtensorMap mapA, mapB;
    encode_2d_f16(enc, &mapA, pA, K_DIM, M_DIM, BK, BM);
    encode_2d_f16(enc, &mapB, pB, K_DIM, N_DIM, BK, BN);

    cudaFuncSetAttribute(agg_gemm_kernel,
                         cudaFuncAttributeMaxDynamicSharedMemorySize, SMEM_BYTES);

    cvt_f16_kernel<<<1184, 256>>>((const float4*)A_in, (__half2*)pA,
                                  (int)(((size_t)M_DIM * K_DIM) / 4));
    cvt_f16_kernel<<<1184, 256>>>((const float4*)W_in, (__half2*)pB,
                                  (int)(((size_t)N_DIM * K_DIM) / 4));

    dim3 grid(N_DIM / BN, M_DIM / BM);   // (32, 64)
    agg_gemm_kernel<<<grid, 256, SMEM_BYTES>>>(mapA, mapB, out);
}

// round 8
// speedup vs baseline: 1.1350x; 1.0126x over previous
#include <cuda_runtime.h>
#include <cuda.h>
#include <cuda_fp16.h>
#include <cstdint>

// ================================================================
// out[8192,4096] = A[8192,4096] (K-major) * W[4096,4096] (K-major)^T
// fp16 mma.sync m16n8k16 + ldmatrix + TMA (SW128), 4-stage
// producer/consumer mbarrier pipeline, CTA 128x256, warp 64x64,
// 1 CTA/SM, no CTA-wide barrier in main loop. fp16 pre-pass.
// ================================================================

#define M_DIM 8192
#define N_DIM 4096
#define K_DIM 4096

#define BM 128
#define BN 256
#define BK 64                        // fp16 per K chunk = 128 B/row
#define STAGES 4
#define NCHUNK (K_DIM / BK)          // 64
#define NWARPS 8

#define A_STAGE_BYTES (BM * 128)     // 16384
#define B_STAGE_BYTES (BN * 128)     // 32768
#define STAGE_BYTES   (A_STAGE_BYTES + B_STAGE_BYTES)      // 49152
#define SMEM_TILE_OFF 1024
#define SMEM_BYTES    (SMEM_TILE_OFF + STAGES * STAGE_BYTES)  // 197632

__device__ __align__(1024) __half g_A[(size_t)M_DIM * K_DIM];
__device__ __align__(1024) __half g_B[(size_t)N_DIM * K_DIM];

__device__ __forceinline__ uint32_t smem_u32(const void* p) {
    uint32_t a;
    asm("{ .reg .u64 t; cvta.to.shared.u64 t, %1; cvt.u32.u64 %0, t; }" : "=r"(a) : "l"(p));
    return a;
}
#define MBARRIER_INIT(a, n) \
    asm volatile("mbarrier.init.shared.b64 [%0], %1;" :: "r"((uint32_t)(a)), "r"((uint32_t)(n)) : "memory")
#define MBARRIER_EXPECT_TX(a, b) \
    asm volatile("mbarrier.arrive.expect_tx.shared.b64 _, [%0], %1;" :: "r"((uint32_t)(a)), "r"((uint32_t)(b)) : "memory")
#define MBARRIER_ARRIVE(a) \
    asm volatile("mbarrier.arrive.shared.b64 _, [%0];" :: "r"((uint32_t)(a)) : "memory")

#define MBARRIER_WAIT_ACQ(a, ph) do {                                               \
    uint32_t _m = (uint32_t)(a), _p = (uint32_t)(ph), _d;                           \
    asm volatile("{\n\t.reg .pred p;\n\t"                                           \
        "mbarrier.try_wait.parity.acquire.cta.shared::cta.b64 p, [%1], %2;\n\t"     \
        "selp.b32 %0, 1, 0, p;\n\t}" : "=r"(_d) : "r"(_m), "r"(_p) : "memory");     \
    if (!_d) {                                                                       \
        asm volatile("{\n\t.reg .pred P1;\n\t"                                      \
            "WL_%=:\n\t"                                                            \
            "mbarrier.try_wait.parity.acquire.cta.shared::cta.b64 P1, [%0], %1, 0x989680;\n\t" \
            "@P1 bra.uni WD_%=;\n\t bra.uni WL_%=;\n\t WD_%=:\n\t}"                 \
            :: "r"(_m), "r"(_p) : "memory");                                        \
    }                                                                                \
} while (0)

#define MBARRIER_WAIT_RLX(a, ph) do {                                               \
    uint32_t _m = (uint32_t)(a), _p = (uint32_t)(ph), _d;                           \
    asm volatile("{\n\t.reg .pred p;\n\t"                                           \
        "mbarrier.try_wait.parity.relaxed.cta.shared::cta.b64 p, [%1], %2, 0x989680;\n\t" \
        "selp.b32 %0, 1, 0, p;\n\t}" : "=r"(_d) : "r"(_m), "r"(_p) : "memory");     \
    if (!_d) {                                                                       \
        asm volatile("{\n\t.reg .pred P1;\n\t"                                      \
            "WL_%=:\n\t"                                                            \
            "mbarrier.try_wait.parity.relaxed.cta.shared::cta.b64 P1, [%0], %1, 0x989680;\n\t" \
            "@P1 bra.uni WD_%=;\n\t bra.uni WL_%=;\n\t WD_%=:\n\t}"                 \
            :: "r"(_m), "r"(_p) : "memory");                                        \
    }                                                                                \
} while (0)

#define TMA_LOAD_2D(smem, map, c0, c1, mbar)                                        \
    asm volatile("cp.async.bulk.tensor.2d.shared::cta.global.tile.mbarrier::complete_tx::bytes " \
        "[%0], [%1, {%2, %3}], [%4];"                                               \
        :: "r"((uint32_t)(smem)), "l"(map), "r"((int)(c0)), "r"((int)(c1)),         \
           "r"((uint32_t)(mbar)) : "memory")

__device__ __forceinline__ void ldsm_x4(uint32_t r[4], uint32_t addr) {
    asm volatile("ldmatrix.sync.aligned.m8n8.x4.shared.b16 {%0,%1,%2,%3}, [%4];"
                 : "=r"(r[0]), "=r"(r[1]), "=r"(r[2]), "=r"(r[3]) : "r"(addr));
}
__device__ __forceinline__ void mma_f16(float c[4], const uint32_t a[4],
                                        uint32_t b0, uint32_t b1) {
    asm volatile(
        "mma.sync.aligned.m16n8k16.row.col.f32.f16.f16.f32 "
        "{%0,%1,%2,%3}, {%4,%5,%6,%7}, {%8,%9}, {%0,%1,%2,%3};"
        : "+f"(c[0]), "+f"(c[1]), "+f"(c[2]), "+f"(c[3])
        : "r"(a[0]), "r"(a[1]), "r"(a[2]), "r"(a[3]), "r"(b0), "r"(b1));
}

__global__ void __launch_bounds__(256) cvt_f16_kernel(
    const float4* __restrict__ in, __half2* __restrict__ out, int n4)
{
    int stride = gridDim.x * blockDim.x;
    for (int i = blockIdx.x * blockDim.x + threadIdx.x; i < n4; i += stride) {
        float4 v = in[i];
        out[2 * i]     = __floats2half2_rn(v.x, v.y);
        out[2 * i + 1] = __floats2half2_rn(v.z, v.w);
    }
}

extern __shared__ char smemc[];

// smem barriers: full[s] = sb + 16*s, empty[s] = sb + 16*s + 8
__global__ void __launch_bounds__(256, 1) agg_gemm_kernel(
    const __grid_constant__ CUtensorMap tma_a,
    const __grid_constant__ CUtensorMap tma_b,
    float* __restrict__ out)
{
    const int t = threadIdx.x;
    const int wid = t >> 5;
    const int lane = t & 31;
    const int wm = wid & 1;          // warp M (0..1): 64 rows
    const int wn = wid >> 1;         // warp N (0..3): 64 cols
    const int g = lane >> 2;
    const int tig = lane & 3;

    const int m0 = blockIdx.y * BM;
    const int n0 = blockIdx.x * BN;

    const uint32_t sb = smem_u32(smemc);
    const uint32_t tiles = sb + SMEM_TILE_OFF;

    if (t == 0) {
        #pragma unroll
        for (int s = 0; s < STAGES; s++) {
            MBARRIER_INIT(sb + 16 * s, 1);           // full: tx-based
            MBARRIER_INIT(sb + 16 * s + 8, NWARPS);  // empty: 8 warp arrives
        }
    }
    __syncthreads();

    int pstage = 0, pphase = 1;      // producer cursor
    auto produce = [&](int chunk) {
        const uint32_t fullb = sb + 16 * pstage;
        MBARRIER_WAIT_RLX(fullb + 8, pphase);
        MBARRIER_EXPECT_TX(fullb, STAGE_BYTES);
        const uint32_t sbase = tiles + (uint32_t)pstage * STAGE_BYTES;
        TMA_LOAD_2D(sbase,                 &tma_a, chunk * BK, m0, fullb);
        TMA_LOAD_2D(sbase + A_STAGE_BYTES, &tma_b, chunk * BK, n0, fullb);
        if (++pstage == STAGES) { pstage = 0; pphase ^= 1; }
    };

    if (t == 0) {
        #pragma unroll
        for (int ps = 0; ps < STAGES - 1; ps++) produce(ps);
    }

    float acc[4][8][4];
    #pragma unroll
    for (int mi = 0; mi < 4; mi++)
        #pragma unroll
        for (int ni = 0; ni < 8; ni++)
            #pragma unroll
            for (int q = 0; q < 4; q++) acc[mi][ni][q] = 0.0f;

    // ldmatrix: row = base + (lane&15); chunk16 ^= (row & 7)
    const int lrow = lane & 15;
    const int lhi = lane >> 4;
    const int lsw = lane & 7;
    const uint32_t a_row_off = (uint32_t)(wm * 64 + lrow) * 128u;
    const uint32_t b_row_off = (uint32_t)A_STAGE_BYTES + (uint32_t)(wn * 64 + lrow) * 128u;

    int cstage = 0, cphase = 0;

    for (int c = 0; c < NCHUNK; c++) {
        const int fetch = c + STAGES - 1;
        if (t == 0 && fetch < NCHUNK) produce(fetch);

        const uint32_t fullb = sb + 16 * cstage;
        MBARRIER_WAIT_ACQ(fullb, cphase);

        const uint32_t sbase = tiles + (uint32_t)cstage * STAGE_BYTES;

        #pragma unroll
        for (int ks = 0; ks < 4; ks++) {
            const uint32_t chunk = (uint32_t)(((ks * 2 + lhi) ^ lsw) * 16);
            uint32_t a[4][4];
            #pragma unroll
            for (int mi = 0; mi < 4; mi++)
                ldsm_x4(a[mi], sbase + a_row_off + (uint32_t)(mi * 16 * 128) + chunk);
            uint32_t b[4][4];
            #pragma unroll
            for (int p = 0; p < 4; p++)
                ldsm_x4(b[p], sbase + b_row_off + (uint32_t)(p * 16 * 128) + chunk);
            #pragma unroll
            for (int mi = 0; mi < 4; mi++) {
                #pragma unroll
                for (int p = 0; p < 4; p++) {
                    mma_f16(acc[mi][2 * p],     a[mi], b[p][0], b[p][2]);
                    mma_f16(acc[mi][2 * p + 1], a[mi], b[p][1], b[p][3]);
                }
            }
        }

        if (lane == 0) MBARRIER_ARRIVE(fullb + 8);
        if (++cstage == STAGES) { cstage = 0; cphase ^= 1; }
    }

    // ---------------- epilogue ----------------
    #pragma unroll
    for (int mi = 0; mi < 4; mi++) {
        const int row = m0 + wm * 64 + mi * 16 + g;
        #pragma unroll
        for (int ni = 0; ni < 8; ni++) {
            const int col = n0 + wn * 64 + ni * 8 + 2 * tig;
            float2 lo = make_float2(acc[mi][ni][0], acc[mi][ni][1]);
            float2 hi = make_float2(acc[mi][ni][2], acc[mi][ni][3]);
            *reinterpret_cast<float2*>(out + (size_t)row * N_DIM + col) = lo;
            *reinterpret_cast<float2*>(out + (size_t)(row + 8) * N_DIM + col) = hi;
        }
    }
}

// ---------------- host ----------------
typedef CUresult (*PFN_EncodeTiled)(
    CUtensorMap*, CUtensorMapDataType, cuuint32_t, void*,
    const cuuint64_t*, const cuuint64_t*, const cuuint32_t*, const cuuint32_t*,
    CUtensorMapInterleave, CUtensorMapSwizzle, CUtensorMapL2promotion, CUtensorMapFloatOOBfill);

static void encode_2d_f16(PFN_EncodeTiled enc, CUtensorMap* map, void* ptr,
                          uint64_t dim0, uint64_t dim1, uint32_t box0, uint32_t box1) {
    cuuint64_t dims[2]    = {dim0, dim1};
    cuuint64_t strides[1] = {dim0 * sizeof(__half)};
    cuuint32_t box[2]     = {box0, box1};
    cuuint32_t estr[2]    = {1, 1};
    enc(map, CU_TENSOR_MAP_DATA_TYPE_FLOAT16, 2, ptr, dims, strides, box, estr,
        CU_TENSOR_MAP_INTERLEAVE_NONE, CU_TENSOR_MAP_SWIZZLE_128B,
        CU_TENSOR_MAP_L2_PROMOTION_L2_128B, CU_TENSOR_MAP_FLOAT_OOB_FILL_NONE);
}

extern "C" void kernel_launch(void* const* d_in, const int* in_sizes, int n_in,
                              void* d_out, int out_size) {
    const float* A_in = (const float*)d_in[0];   // [8,1024,4096] = [8192,4096]
    const float* W_in = (const float*)d_in[1];   // [4096,4096] K-major
    float* out = (float*)d_out;

    void *pA = nullptr, *pB = nullptr;
    cudaGetSymbolAddress(&pA, g_A);
    cudaGetSymbolAddress(&pB, g_B);

    void* fn = nullptr;
    cudaDriverEntryPointQueryResult st;
    cudaGetDriverEntryPointByVersion("cuTensorMapEncodeTiled", &fn, 12000,
                                     cudaEnableDefault, &st);
    PFN_EncodeTiled enc = (PFN_EncodeTiled)fn;

    CUtensorMap mapA, mapB;
    encode_2d_f16(enc, &mapA, pA, K_DIM, M_DIM, BK, BM);
    encode_2d_f16(enc, &mapB, pB, K_DIM, N_DIM, BK, BN);

    cudaFuncSetAttribute(agg_gemm_kernel,
                         cudaFuncAttributeMaxDynamicSharedMemorySize, SMEM_BYTES);

    cvt_f16_kernel<<<1184, 256>>>((const float4*)A_in, (__half2*)pA,
                                  (int)(((size_t)M_DIM * K_DIM) / 4));
    cvt_f16_kernel<<<1184, 256>>>((const float4*)W_in, (__half2*)pB,
                                  (int)(((size_t)N_DIM * K_DIM) / 4));

    dim3 grid(N_DIM / BN, M_DIM / BM);   // (16, 64)
    agg_gemm_kernel<<<grid, 256, SMEM_BYTES>>>(mapA, mapB, out);
}